// round 7
// baseline (speedup 1.0000x reference)
#include <cuda_runtime.h>
#include <cstdint>

#define DD 160
#define NN 82944
#define BB 4
#define NT 128
#define NBLK 648            /* tiles (columns/NT) per batch */
#define RS 128              /* tile row stride in floats (512B, 16B aligned) */
#define EPSV 1e-6f
#define NBLKF 162           /* NN / 512 for float2 final kernel (256 thr x 2) */

#define PBLKS 144           /* persistent blocks: 2592 tiles / 18 */
#define TPB 18              /* tiles per block */
#define BLKS_PER_B 36       /* NBLK / TPB */
#define TILEF (DD * RS)     /* floats per tile buffer */

// Scratch state (device globals: no allocation allowed)
__device__ float g_c[BB * NN];          // coef
__device__ float g_v[BB * DD];          // bases vector
__device__ float g_s[BB];               // ||v||^2
__device__ float g_wp[BB * NBLK * DD];  // per-tile partials of w = X c
__device__ float g_tp[BB * NBLK];       // per-tile partials of t = ||c||^2

// ---------------------------------------------------------------------------
// cp.async helpers (LDGSTS on sm_103a)
// ---------------------------------------------------------------------------
__device__ __forceinline__ void cpasync16(uint32_t dst, const void* src) {
    asm volatile("cp.async.cg.shared.global [%0], [%1], 16;\n" :: "r"(dst), "l"(src));
}
__device__ __forceinline__ void cpcommit() {
    asm volatile("cp.async.commit_group;\n" ::: "memory");
}
template <int N>
__device__ __forceinline__ void cpwait() {
    asm volatile("cp.async.wait_group %0;\n" :: "n"(N) : "memory");
}

// ---------------------------------------------------------------------------
// init: v = bases, s = ||v||^2
// ---------------------------------------------------------------------------
__global__ void init_kernel(const float* __restrict__ bases) {
    int b = blockIdx.x, d = threadIdx.x;
    __shared__ float sh[DD];
    float v = bases[b * DD + d];
    g_v[b * DD + d] = v;
    sh[d] = v * v;
    __syncthreads();
    if (d == 0) {
        float s = 0.f;
        for (int i = 0; i < DD; i++) s += sh[i];
        g_s[b] = s;
    }
}

// ---------------------------------------------------------------------------
// One NMF step: persistent blocks, double-buffered cp.async tile pipeline.
// Each of 144 blocks owns 18 consecutive 160x128 tiles of one batch.
// While computing tile i from SMEM, tile i+1 streams in via LDGSTS.
// ---------------------------------------------------------------------------
__global__ void __launch_bounds__(NT, 1) step_kernel(const float* __restrict__ x,
                                                     int first) {
    __shared__ float v_sh[DD];
    __shared__ float c_sh[NT];
    __shared__ float red[4];
    extern __shared__ float buf[];  // 2 * TILEF floats = 160 KB

    int p = blockIdx.x, tid = threadIdx.x;
    int lane = tid & 31, wid = tid >> 5;
    int b = p / BLKS_PER_B;
    int blk0 = (p % BLKS_PER_B) * TPB;

    for (int i = tid; i < DD; i += NT) v_sh[i] = g_v[b * DD + i];
    float s = g_s[b];

    // Per-thread fixed (row-within-slab, 16B chunk) for the copy engine.
    int drow = tid >> 5;                 // 0..3
    int ch4 = (tid & 31) * 4;            // float offset of 16B chunk
    const float* gbase = x + (size_t)b * DD * NN + (size_t)drow * NN + ch4;
    uint32_t sbase = (uint32_t)__cvta_generic_to_shared(buf);
    uint32_t sthr = sbase + (uint32_t)(drow * RS + ch4) * 4u;

#define ISSUE_TILE(t)                                                        \
    do {                                                                     \
        const float* gsrc = gbase + (size_t)(blk0 + (t)) * NT;               \
        uint32_t sdst = sthr + (uint32_t)(((t)&1) * TILEF) * 4u;             \
        _Pragma("unroll")                                                    \
        for (int it = 0; it < 40; it++) {                                    \
            cpasync16(sdst + (uint32_t)(it * 4 * RS) * 4u,                   \
                      gsrc + (size_t)(it * 4) * NN);                         \
        }                                                                    \
        cpcommit();                                                          \
    } while (0)

    ISSUE_TILE(0);
    __syncthreads();  // v_sh visible before compute

    for (int i = 0; i < TPB; i++) {
        if (i + 1 < TPB) {
            ISSUE_TILE(i + 1);
            cpwait<1>();
        } else {
            cpwait<0>();
        }
        __syncthreads();

        const float* tile = buf + (i & 1) * TILEF;
        int blk = blk0 + i;

        // Pass 1: u[n] = sum_d X[d,n] v[d]
        float u0 = 0.f, u1 = 0.f, u2 = 0.f, u3 = 0.f;
#pragma unroll 8
        for (int d = 0; d < DD; d += 4) {
            u0 = fmaf(tile[(d + 0) * RS + tid], v_sh[d + 0], u0);
            u1 = fmaf(tile[(d + 1) * RS + tid], v_sh[d + 1], u1);
            u2 = fmaf(tile[(d + 2) * RS + tid], v_sh[d + 2], u2);
            u3 = fmaf(tile[(d + 3) * RS + tid], v_sh[d + 3], u3);
        }
        float u = (u0 + u1) + (u2 + u3);

        size_t cidx = (size_t)b * NN + (size_t)blk * NT + tid;
        float cold = first ? 1.f : g_c[cidx];
        float cn = cold * u / (cold * s + EPSV);
        g_c[cidx] = cn;
        c_sh[tid] = cn;

        // t-partial: block reduce cn^2
        float tv = cn * cn;
#pragma unroll
        for (int off = 16; off; off >>= 1)
            tv += __shfl_xor_sync(0xffffffffu, tv, off);
        if (lane == 0) red[wid] = tv;
        __syncthreads();
        if (tid == 0) g_tp[b * NBLK + blk] = red[0] + red[1] + red[2] + red[3];

        // Pass 2: w[d] partial = sum_n tile[d][n]*cn[n]  (float4 per lane)
        const float4 cc = *reinterpret_cast<const float4*>(&c_sh[lane * 4]);
        float* wp = g_wp + ((size_t)b * NBLK + blk) * DD;
        for (int d = wid; d < DD; d += 4) {
            float4 xv = *reinterpret_cast<const float4*>(&tile[d * RS + lane * 4]);
            float acc = fmaf(xv.x, cc.x,
                        fmaf(xv.y, cc.y, fmaf(xv.z, cc.z, xv.w * cc.w)));
#pragma unroll
            for (int off = 16; off; off >>= 1)
                acc += __shfl_xor_sync(0xffffffffu, acc, off);
            if (lane == 0) wp[d] = acc;
        }
        __syncthreads();  // protect buffer before reissue next iteration
    }
#undef ISSUE_TILE
}

// ---------------------------------------------------------------------------
// v update: reduce partials deterministically, v = v*w/(v*t+eps), s = ||v||^2
// ---------------------------------------------------------------------------
__global__ void vupdate_kernel() {
    __shared__ float shw[640];
    __shared__ float sht[DD];
    __shared__ float shs[DD];
    __shared__ float t_tot;
    int b = blockIdx.x, tid = threadIdx.x;
    int d = tid % DD, chunk = tid / DD;  // 4 chunks x 162 tiles each

    float wsum = 0.f;
    int k0 = chunk * 162;
    for (int k = k0; k < k0 + 162; k++)
        wsum += g_wp[((size_t)b * NBLK + k) * DD + d];
    shw[chunk * DD + d] = wsum;

    if (tid < DD) {
        float ts = 0.f;
        for (int k = tid; k < NBLK; k += DD) ts += g_tp[b * NBLK + k];
        sht[tid] = ts;
    }
    __syncthreads();
    if (tid == 0) {
        float t = 0.f;
        for (int i = 0; i < DD; i++) t += sht[i];
        t_tot = t;
    }
    __syncthreads();
    if (tid < DD) {
        float wfull = shw[tid] + shw[tid + DD] + shw[tid + 2 * DD] + shw[tid + 3 * DD];
        float vd = g_v[b * DD + tid];
        float vn = vd * wfull / (vd * t_tot + EPSV);
        g_v[b * DD + tid] = vn;
        shs[tid] = vn * vn;
    }
    __syncthreads();
    if (tid == 0) {
        float s = 0.f;
        for (int i = 0; i < DD; i++) s += shs[i];
        g_s[b] = s;
    }
}

// ---------------------------------------------------------------------------
// Final: u = X^T v, c' = c*u/(c*s+eps), out = v c'^T.
// float2 per thread, 256-thread blocks.
// ---------------------------------------------------------------------------
__global__ void __launch_bounds__(256) final_kernel(const float* __restrict__ x,
                                                    float* __restrict__ out) {
    __shared__ float v_sh[DD];
    int b = blockIdx.y, tid = threadIdx.x;
    size_t n0 = (size_t)blockIdx.x * 512 + (size_t)tid * 2;

    for (int i = tid; i < DD; i += 256) v_sh[i] = g_v[b * DD + i];
    __syncthreads();
    float s = g_s[b];

    const float* xb = x + (size_t)b * DD * NN + n0;
    float* ob = out + (size_t)b * DD * NN + n0;

    float ux = 0.f, uy = 0.f;
#pragma unroll 8
    for (int d = 0; d < DD; d++) {
        float2 xv = *reinterpret_cast<const float2*>(xb + (size_t)d * NN);
        float vd = v_sh[d];
        ux = fmaf(xv.x, vd, ux);
        uy = fmaf(xv.y, vd, uy);
    }

    float2 co = *reinterpret_cast<const float2*>(g_c + (size_t)b * NN + n0);
    float cnx = co.x * ux / (co.x * s + EPSV);
    float cny = co.y * uy / (co.y * s + EPSV);

#pragma unroll 8
    for (int d = 0; d < DD; d++) {
        float vd = v_sh[d];
        float2 o = make_float2(vd * cnx, vd * cny);
        *reinterpret_cast<float2*>(ob + (size_t)d * NN) = o;
    }
}

// ---------------------------------------------------------------------------
extern "C" void kernel_launch(void* const* d_in, const int* in_sizes, int n_in,
                              void* d_out, int out_size) {
    const float* x = (const float*)d_in[0];
    const float* bases = (const float*)d_in[1];
    float* out = (float*)d_out;

    cudaFuncSetAttribute(step_kernel, cudaFuncAttributeMaxDynamicSharedMemorySize,
                         2 * TILEF * (int)sizeof(float));

    init_kernel<<<BB, DD>>>(bases);
    for (int s = 0; s < 4; s++) {
        step_kernel<<<PBLKS, NT, 2 * TILEF * sizeof(float)>>>(x, s == 0);
        vupdate_kernel<<<BB, 640>>>();
    }
    final_kernel<<<dim3(NBLKF, BB), 256>>>(x, out);
}